// round 5
// baseline (speedup 1.0000x reference)
#include <cuda_runtime.h>

// ---------------------------------------------------------------------------
// SpatioTemporalGNNLayer: out = relu(conv3x3(x,Ww)+Wb + conv3x3(agg,Bw)+Bb)
// agg[dst] = mean over incoming edges of x[src].
//
// CSR build (prep -> count -> scan+fill), then one fused per-node kernel:
// gather-mean + both convs via fma.rn.f32x2 with dual-alignment smem rows,
// 4x output-channel blocking, fully vectorized LDS, two-phase weight staging.
// ---------------------------------------------------------------------------

#define NNODES 4096
#define NODE_ELEMS 4096          // 16*16*16
#define RS 36                    // row: [0,x0..x15,0,pad,pad | x0..x15] (144B)
#define CHS (18*RS)              // 18 rows (zero row above+below) = 648 floats
#define IMG_FLOATS (32*CHS)      // 20736 (x image 16ch + agg image 16ch)
#define WP_FLOAT2 2304           // duplicated weight pairs for one conv
#define NMASK (NNODES-1)

__device__ int g_deg[NNODES];
__device__ int g_cur[NNODES];
__device__ int g_off[NNODES + 1];
__device__ int g_srcs[16384 * 4];   // headroom for E
__device__ int g_is64;

// ---------------------------------------------------------------------------
__global__ void prep_kernel(const int* __restrict__ ei32, int E) {
    int i = blockIdx.x * blockDim.x + threadIdx.x;
    if (i < NNODES) { g_deg[i] = 0; g_cur[i] = 0; }
    if (blockIdx.x == 0 && threadIdx.x < 32) {
        int n = (E < 32) ? E : 32;
        int odd = (threadIdx.x < n) ? ei32[2 * threadIdx.x + 1] : 0;
        unsigned nz = __ballot_sync(0xffffffffu, odd != 0);
        if (threadIdx.x == 0) g_is64 = (nz == 0);
    }
}

__device__ __forceinline__ int load_idx(const int* ei32, int pos) {
    return g_is64 ? (ei32[2 * pos] & NMASK) : (ei32[pos] & NMASK);
}

__global__ void count_kernel(const int* __restrict__ ei32, int E) {
    int e = blockIdx.x * blockDim.x + threadIdx.x;
    if (e < E) atomicAdd(&g_deg[load_idx(ei32, E + e)], 1);
}

__global__ void scanfill_kernel(const int* __restrict__ ei32, int E) {
    __shared__ int wsum[32];
    int t = threadIdx.x;
    int lane = t & 31, wid = t >> 5;
    int4 v = ((const int4*)g_deg)[t];
    int sum = v.x + v.y + v.z + v.w;
    int s = sum;
#pragma unroll
    for (int d = 1; d < 32; d <<= 1) {
        int n = __shfl_up_sync(0xffffffffu, s, d);
        if (lane >= d) s += n;
    }
    if (lane == 31) wsum[wid] = s;
    __syncthreads();
    if (wid == 0) {
        int ws = wsum[lane];
#pragma unroll
        for (int d = 1; d < 32; d <<= 1) {
            int n = __shfl_up_sync(0xffffffffu, ws, d);
            if (lane >= d) ws += n;
        }
        wsum[lane] = ws;
    }
    __syncthreads();
    int excl = ((wid > 0) ? wsum[wid - 1] : 0) + s - sum;
    g_off[4 * t + 0] = excl;
    g_off[4 * t + 1] = excl + v.x;
    g_off[4 * t + 2] = excl + v.x + v.y;
    g_off[4 * t + 3] = excl + v.x + v.y + v.z;
    if (t == 1023) g_off[NNODES] = wsum[31];
    __syncthreads();
    for (int e = t; e < E; e += 1024) {
        int sc = load_idx(ei32, e);
        int d  = load_idx(ei32, E + e);
        int pos = g_off[d] + atomicAdd(&g_cur[d], 1);
        g_srcs[pos] = sc;
    }
}

// ---------------------------------------------------------------------------
__device__ __forceinline__ float2 ffma2(float2 a, float2 b, float2 c) {
    float2 d;
    asm("{\n\t"
        ".reg .b64 ta, tb, tc;\n\t"
        "mov.b64 ta, {%2, %3};\n\t"
        "mov.b64 tb, {%4, %5};\n\t"
        "mov.b64 tc, {%6, %7};\n\t"
        "fma.rn.f32x2 tc, ta, tb, tc;\n\t"
        "mov.b64 {%0, %1}, tc;\n\t"
        "}"
        : "=f"(d.x), "=f"(d.y)
        : "f"(a.x), "f"(a.y), "f"(b.x), "f"(b.y), "f"(c.x), "f"(c.y));
    return d;
}

// One conv over one 16-channel image for this thread's 4 output channels and
// 8 pixels (pixel pairs j=0..3 at x = 8*half + 2j).
// Row layout (36 floats): [0, x0..x15, 0, pad, pad, x0..x15]
//   P pairs (taps -1/+1) at words 0..17, S pairs (tap 0) at words 20..35.
// Weight pairs wp[(ci*9 + 3r + t)*16 + co] = (w,w).
__device__ __forceinline__ void conv_phase(const float* __restrict__ img,
                                           const float2* __restrict__ wp,
                                           int row, int half, int co_base,
                                           float2 acc[4][4]) {
#pragma unroll 1
    for (int ci = 0; ci < 16; ci++) {
        const float* ch = img + ci * CHS;
#pragma unroll
        for (int r = 0; r < 3; r++) {
            const float* rp = ch + (row + r) * RS + 8 * half;
            float4 p01 = *(const float4*)rp;
            float4 p23 = *(const float4*)(rp + 4);
            float2 p4  = *(const float2*)(rp + 8);
            float4 s01 = *(const float4*)(rp + 20);
            float4 s23 = *(const float4*)(rp + 24);
            float2 P[5] = { make_float2(p01.x, p01.y), make_float2(p01.z, p01.w),
                            make_float2(p23.x, p23.y), make_float2(p23.z, p23.w),
                            p4 };
            float2 S[4] = { make_float2(s01.x, s01.y), make_float2(s01.z, s01.w),
                            make_float2(s23.x, s23.y), make_float2(s23.z, s23.w) };
            const float2* wrow = wp + (ci * 9 + 3 * r) * 16 + co_base;
#pragma unroll
            for (int t = 0; t < 3; t++) {
                float4 wlo = *(const float4*)(wrow + t * 16);
                float4 whi = *(const float4*)(wrow + t * 16 + 2);
                float2 w[4] = { make_float2(wlo.x, wlo.y), make_float2(wlo.z, wlo.w),
                                make_float2(whi.x, whi.y), make_float2(whi.z, whi.w) };
#pragma unroll
                for (int c = 0; c < 4; c++) {
#pragma unroll
                    for (int j = 0; j < 4; j++) {
                        float2 op = (t == 0) ? P[j] : (t == 1) ? S[j] : P[j + 1];
                        acc[c][j] = ffma2(w[c], op, acc[c][j]);
                    }
                }
            }
        }
    }
}

__global__ __launch_bounds__(128, 2) void gnn_main_kernel(
    const float* __restrict__ x,
    const float* __restrict__ Ww, const float* __restrict__ Wbias,
    const float* __restrict__ Bw, const float* __restrict__ Bbias,
    float* __restrict__ out) {
    extern __shared__ float sm[];
    float*  sImg = sm;                       // 20736 floats
    float2* sWp  = (float2*)(sm + IMG_FLOATS);  // 2304 float2 (one conv's pairs)

    int tid  = threadIdx.x;
    int node = blockIdx.x;

    // zero image buffers (pads stay 0; data regions overwritten later)
    float4* z4 = (float4*)sImg;
    for (int i = tid; i < IMG_FLOATS / 4; i += 128)
        z4[i] = make_float4(0.f, 0.f, 0.f, 0.f);
    // stage phase-A (Ww) duplicated weight pairs
    for (int i = tid; i < WP_FLOAT2; i += 128) {
        int co = i & 15, q = i >> 4;           // q = ci*9 + 3r + t
        float v = Ww[co * 144 + q];
        sWp[i] = make_float2(v, v);
    }

    // gather-mean over incoming edges: 8 float4 per thread (regs)
    const float4* xp = (const float4*)(x + (size_t)node * NODE_ELEMS);
    float4 a[8];
#pragma unroll
    for (int k = 0; k < 8; k++) a[k] = make_float4(0.f, 0.f, 0.f, 0.f);
    int beg = g_off[node], end = g_off[node + 1];
    for (int e = beg; e < end; e++) {
        int sc = g_srcs[e] & NMASK;
        const float4* sp = (const float4*)(x + (size_t)sc * NODE_ELEMS);
#pragma unroll
        for (int k = 0; k < 8; k++) {
            float4 v = __ldg(&sp[tid + 128 * k]);
            a[k].x += v.x; a[k].y += v.y; a[k].z += v.z; a[k].w += v.w;
        }
    }
    float inv = 1.0f / (float)max(end - beg, 1);

    __syncthreads();   // zeros + Ww pairs in place

    // scatter x + agg into dual-alignment rows
#pragma unroll
    for (int k = 0; k < 8; k++) {
        int i4  = tid + 128 * k;
        int ci  = i4 >> 6;
        int rem = i4 & 63;
        int y   = rem >> 2;
        int m   = (rem & 3) * 4;
        float* bx = sImg + ci * CHS + (y + 1) * RS;
        float* ba = sImg + (16 + ci) * CHS + (y + 1) * RS;
        float4 xv = xp[i4];
        bx[1 + m] = xv.x; bx[2 + m] = xv.y; bx[3 + m] = xv.z; bx[4 + m] = xv.w;
        *(float4*)(bx + 20 + m) = xv;
        float4 av = make_float4(a[k].x * inv, a[k].y * inv, a[k].z * inv, a[k].w * inv);
        ba[1 + m] = av.x; ba[2 + m] = av.y; ba[3 + m] = av.z; ba[4 + m] = av.w;
        *(float4*)(ba + 20 + m) = av;
    }
    __syncthreads();

    // thread = (half, cog, row): 2 x 4 x 16 = 128
    int row  = tid & 15;
    int cog  = (tid >> 4) & 3;
    int half = tid >> 6;
    int co_base = cog * 4;

    float2 acc[4][4];
#pragma unroll
    for (int c = 0; c < 4; c++) {
        float bz = __ldg(&Wbias[co_base + c]) + __ldg(&Bbias[co_base + c]);
#pragma unroll
        for (int j = 0; j < 4; j++) acc[c][j] = make_float2(bz, bz);
    }

    // phase A: conv(x, Ww)
    conv_phase(sImg, sWp, row, half, co_base, acc);

    __syncthreads();   // done reading Ww pairs
    // stage phase-B (Bw) pairs
    for (int i = tid; i < WP_FLOAT2; i += 128) {
        int co = i & 15, q = i >> 4;
        float v = Bw[co * 144 + q];
        sWp[i] = make_float2(v, v);
    }
    __syncthreads();

    // phase B: conv(agg, Bw)
    conv_phase(sImg + 16 * CHS, sWp, row, half, co_base, acc);

    // relu + store
#pragma unroll
    for (int c = 0; c < 4; c++) {
        float* o = out + (size_t)node * NODE_ELEMS + (co_base + c) * 256
                   + row * 16 + 8 * half;
        ((float4*)o)[0] = make_float4(fmaxf(acc[c][0].x, 0.f), fmaxf(acc[c][0].y, 0.f),
                                      fmaxf(acc[c][1].x, 0.f), fmaxf(acc[c][1].y, 0.f));
        ((float4*)o)[1] = make_float4(fmaxf(acc[c][2].x, 0.f), fmaxf(acc[c][2].y, 0.f),
                                      fmaxf(acc[c][3].x, 0.f), fmaxf(acc[c][3].y, 0.f));
    }
}

// ---------------------------------------------------------------------------
extern "C" void kernel_launch(void* const* d_in, const int* in_sizes, int n_in,
                              void* d_out, int out_size) {
    const float* x   = (const float*)d_in[0];
    const int*   ei  = (const int*)d_in[1];   // int32 view; prep detects dtype
    const float* Ww  = (const float*)d_in[2];
    const float* Wb  = (const float*)d_in[3];
    const float* Bw  = (const float*)d_in[4];
    const float* Bb  = (const float*)d_in[5];
    float*       out = (float*)d_out;

    int E = in_sizes[1] / 2;
    int N = in_sizes[0] / NODE_ELEMS;

    prep_kernel<<<(NNODES + 255) / 256, 256>>>(ei, E);
    count_kernel<<<(E + 255) / 256, 256>>>(ei, E);
    scanfill_kernel<<<1, 1024>>>(ei, E);

    int smem_bytes = (IMG_FLOATS + 2 * WP_FLOAT2) * (int)sizeof(float);  // 101376
    cudaFuncSetAttribute(gnn_main_kernel,
                         cudaFuncAttributeMaxDynamicSharedMemorySize, smem_bytes);
    gnn_main_kernel<<<N, 128, smem_bytes>>>(x, Ww, Wb, Bw, Bb, out);
}